// round 8
// baseline (speedup 1.0000x reference)
#include <cuda_runtime.h>
#include <cuda_fp16.h>

#define BB 256
#define TT 1024
#define HH 64
#define GG 256
#define NL 5
#define CPL 16
#define RPC 16
#define AST 72
#define NRING 8
#define LSTM_CTAS (NL * CPL)      // 80
#define FC_CTAS 64
#define GRID_ALL (LSTM_CTAS + FC_CTAS)   // 144 <= 148 SMs

__device__ float g_h[NL][(size_t)BB * TT * HH];
__device__ int   g_flags[NL][CPL];

__device__ __forceinline__ float sigf(float x) {
    x = fminf(fmaxf(x, -30.f), 30.f);
    return __fdividef(1.0f, 1.0f + __expf(-x));
}
__device__ __forceinline__ float tanhf_fast(float x) {
    x = fminf(fmaxf(x, -15.f), 15.f);
    float e = __expf(-2.0f * x);
    return __fdividef(1.0f - e, 1.0f + e);
}
__device__ __forceinline__ int ld_acquire(const int* p) {
    int v;
    asm volatile("ld.global.acquire.gpu.b32 %0, [%1];" : "=r"(v) : "l"(p) : "memory");
    return v;
}
__device__ __forceinline__ void st_release(int* p, int v) {
    asm volatile("st.global.release.gpu.b32 [%0], %1;" :: "l"(p), "r"(v) : "memory");
}
__global__ void reset_flags() {
    int i = threadIdx.x;
    if (i < NL * CPL) ((int*)g_flags)[i] = 0;
}

#define MMA(d0, d1, d2, d3, a0, a1, a2, a3, b0, b1)                        \
    asm volatile(                                                          \
        "mma.sync.aligned.m16n8k16.row.col.f32.f16.f16.f32 "               \
        "{%0,%1,%2,%3}, {%4,%5,%6,%7}, {%8,%9}, {%0,%1,%2,%3};"            \
        : "+f"(d0), "+f"(d1), "+f"(d2), "+f"(d3)                           \
        : "r"(a0), "r"(a1), "r"(a2), "r"(a3), "r"(b0), "r"(b1))

__device__ __forceinline__ void split2(float x, __half& hi, __half& lo) {
    hi = __float2half_rn(x);
    lo = __float2half_rn(x - __half2float(hi));
}
__device__ __forceinline__ unsigned packh(__half a, __half b) {
    __half2 h = __halves2half2(a, b);
    return *reinterpret_cast<unsigned*>(&h);
}
__device__ __forceinline__ void sts_pair(__half* dh, __half* dl, float2 v) {
    __half h0, l0, h1, l1;
    split2(v.x, h0, l0); split2(v.y, h1, l1);
    *reinterpret_cast<unsigned*>(dh) = packh(h0, h1);
    *reinterpret_cast<unsigned*>(dl) = packh(l0, l1);
}

// Overlaid smem: LSTM CTAs and FC CTAs use the same static buffer.
struct LstmSmem {
    __half Hh[2][RPC][AST], Hl[2][RPC][AST];        // own h (hi/lo)
    __half Xh[NRING][RPC][AST], Xl[NRING][RPC][AST];// h_prev ring
    float  xs0[NRING][RPC];                         // layer-0 x ring
};
struct FcSmem {
    float W1T[64 * 64];
    float b1s[64], w2s[64];
    float hsm[8][64];
};
#define SMEM_BYTES (sizeof(LstmSmem) > sizeof(FcSmem) ? sizeof(LstmSmem) : sizeof(FcSmem))

// ---------------------------------------------------------------------------
// 144 CTAs: [0,80) = 5 LSTM layers x 16 chunks (tensor-core wavefront, skew 8)
//           [80,144) = FC-head consumers trailing layer 4 by 64-step blocks.
// ---------------------------------------------------------------------------
__global__ void __launch_bounds__(256, 1)
wavefront(const float* __restrict__ x,     // [B,T]
          const float* __restrict__ wih0,  // [256]
          const float* __restrict__ wihR,  // [4,256,64]
          const float* __restrict__ whh,   // [5,256,64]
          const float* __restrict__ bih,   // [5,256]
          const float* __restrict__ bhh,   // [5,256]
          const float* __restrict__ W1, const float* __restrict__ b1,
          const float* __restrict__ W2, const float* __restrict__ b2,
          float* __restrict__ out)         // [B*T]
{
    __shared__ __align__(16) char smraw[SMEM_BYTES];
    const int tid = threadIdx.x;
    const int bid = blockIdx.x;

    if (bid >= LSTM_CTAS) {
        // ========================= FC consumers =========================
        FcSmem* sm = reinterpret_cast<FcSmem*>(smraw);
        for (int i = tid; i < 4096; i += 256) {
            int j = i >> 6, k = i & 63;
            sm->W1T[k * 64 + j] = W1[j * 64 + k];
        }
        if (tid < 64) {
            sm->b1s[tid] = b1[tid];
            sm->w2s[tid] = W2[tid];
        }
        __syncthreads();
        const float b2v = b2[0];
        const int fcid = bid - LSTM_CTAS;     // 0..63
        const int ch4  = fcid >> 2;           // layer-4 chunk
        const int r0f  = fcid * 4;            // 4 batch rows
        const int* pf4 = &g_flags[NL - 1][ch4];
        const float* h4 = g_h[NL - 1];
        const int warp = tid >> 5, lane = tid & 31;

        for (int tb = 0; tb < TT; tb += 64) {
            int need = tb + 64;
            while (ld_acquire(pf4) < need) __nanosleep(256);
            #pragma unroll 1
            for (int j = 0; j < 32; ++j) {
                int idx = warp * 32 + j;            // 0..255
                int r = idx >> 6, dt = idx & 63;
                size_t p = (size_t)(r0f + r) * TT + tb + dt;
                float h0 = fmaxf(__ldcg(h4 + p * 64 + lane), 0.f);
                float h1 = fmaxf(__ldcg(h4 + p * 64 + 32 + lane), 0.f);
                sm->hsm[warp][lane] = h0;
                sm->hsm[warp][lane + 32] = h1;
                __syncwarp();
                float y0 = sm->b1s[lane], y1 = sm->b1s[lane + 32];
                #pragma unroll
                for (int k = 0; k < 64; k++) {
                    float hv = sm->hsm[warp][k];
                    y0 = fmaf(sm->W1T[k * 64 + lane], hv, y0);
                    y1 = fmaf(sm->W1T[k * 64 + lane + 32], hv, y1);
                }
                float part = fmaxf(y0, 0.f) * sm->w2s[lane] +
                             fmaxf(y1, 0.f) * sm->w2s[lane + 32];
                #pragma unroll
                for (int o = 16; o; o >>= 1)
                    part += __shfl_down_sync(~0u, part, o);
                if (!lane) out[p] = part + b2v;
                __syncwarp();
            }
        }
        return;
    }

    // =========================== LSTM wavefront ===========================
    LstmSmem* sm = reinterpret_cast<LstmSmem*>(smraw);
    const int w   = tid >> 5, ln = tid & 31;
    const int li  = bid / CPL, ch = bid % CPL;
    const int r0  = ch * RPC;
    const bool L0 = (li == 0);
    const int rA = ln >> 2;
    const int cc = (ln & 3) * 2;
    const int u0 = 8 * w + cc;
    const int NKT = L0 ? 4 : 8;

    unsigned bhi[4][8][2], blo[4][8][2];
    #pragma unroll
    for (int gi = 0; gi < 4; gi++) {
        const int grow = gi * 64 + 8 * w + rA;
        #pragma unroll
        for (int kt = 0; kt < 8; kt++)
            #pragma unroll
            for (int hf = 0; hf < 2; hf++) {
                bhi[gi][kt][hf] = 0; blo[gi][kt][hf] = 0;
                if (kt < NKT) {
                    int kg = ((kt < 4) ? kt * 16 : (kt - 4) * 16) + cc + hf * 8;
                    const float* src = (kt < 4)
                        ? whh  + ((size_t)li * GG + grow) * HH + kg
                        : wihR + ((size_t)(li - 1) * GG + grow) * HH + kg;
                    float2 wv = *reinterpret_cast<const float2*>(src);
                    __half h0, l0, h1, l1;
                    split2(wv.x, h0, l0); split2(wv.y, h1, l1);
                    bhi[gi][kt][hf] = packh(h0, h1);
                    blo[gi][kt][hf] = packh(l0, l1);
                }
            }
    }
    float bs[4][2], ws[4][2];
    #pragma unroll
    for (int gi = 0; gi < 4; gi++)
        #pragma unroll
        for (int e = 0; e < 2; e++) {
            int gu = gi * 64 + u0 + e;
            bs[gi][e] = bih[li * GG + gu] + bhh[li * GG + gu];
            ws[gi][e] = L0 ? wih0[gu] : 0.f;
        }

    for (int i = tid; i < RPC * AST; i += 256) {
        (&sm->Hh[0][0][0])[i] = __float2half(0.f);
        (&sm->Hl[0][0][0])[i] = __float2half(0.f);
    }

    const int srow = tid >> 5;
    const int su   = 2 * ln;
    const size_t pb0 = ((size_t)(r0 + srow) * TT) * 64 + su;
    const size_t pb1 = ((size_t)(r0 + srow + 8) * TT) * 64 + su;
    const int* pf = li ? &g_flags[li - 1][ch] : nullptr;
    int* myf = &g_flags[li][ch];
    const float* hp = li ? g_h[li - 1] : nullptr;
    float* ho = g_h[li];
    float2 q0 = make_float2(0.f, 0.f), q1 = make_float2(0.f, 0.f);
    float qx = 0.f;

    // prologue: fill 6 ring slots + 1 in regs (skew 8)
    if (!L0) {
        while (ld_acquire(pf) < 6) __nanosleep(128);
        #pragma unroll
        for (int s = 0; s < 6; s++) {
            sts_pair(&sm->Xh[s][srow][su],     &sm->Xl[s][srow][su],
                     *(const float2*)(hp + pb0 + (size_t)s * 64));
            sts_pair(&sm->Xh[s][srow + 8][su], &sm->Xl[s][srow + 8][su],
                     *(const float2*)(hp + pb1 + (size_t)s * 64));
        }
        while (ld_acquire(pf) < 7) __nanosleep(128);
        q0 = *(const float2*)(hp + pb0 + 6 * 64);
        q1 = *(const float2*)(hp + pb1 + 6 * 64);
    } else if (tid < RPC) {
        const float* xp = x + (size_t)(r0 + tid) * TT;
        #pragma unroll
        for (int s = 0; s < 6; s++) sm->xs0[s][tid] = xp[s];
        qx = xp[6];
    }
    float c0 = 0.f, c1 = 0.f, c2 = 0.f, c3 = 0.f;
    __syncthreads();

    for (int t = 0; t < TT; ++t) {
        // early flag sample: consumed after the update (latency hidden)
        int fl = 0x7fffffff;
        if (!L0 && t + 7 < TT) fl = ld_acquire(pf);

        float d[4][4];
        #pragma unroll
        for (int gi = 0; gi < 4; gi++) {
            d[gi][0] = bs[gi][0]; d[gi][1] = bs[gi][1];
            d[gi][2] = bs[gi][0]; d[gi][3] = bs[gi][1];
        }
        const __half* HhT = &sm->Hh[t & 1][0][0];
        const __half* HlT = &sm->Hl[t & 1][0][0];
        const __half* XhT = &sm->Xh[t & (NRING - 1)][0][0];
        const __half* XlT = &sm->Xl[t & (NRING - 1)][0][0];
        #pragma unroll
        for (int kt = 0; kt < 8; kt++) {
            if (L0 && kt >= 4) break;
            const __half *Ah, *Al; int k0;
            if (kt < 4) { Ah = HhT; Al = HlT; k0 = kt * 16; }
            else        { Ah = XhT; Al = XlT; k0 = (kt - 4) * 16; }
            unsigned a0 = *(const unsigned*)(Ah + rA * AST + k0 + cc);
            unsigned a1 = *(const unsigned*)(Ah + (rA + 8) * AST + k0 + cc);
            unsigned a2 = *(const unsigned*)(Ah + rA * AST + k0 + cc + 8);
            unsigned a3 = *(const unsigned*)(Ah + (rA + 8) * AST + k0 + cc + 8);
            unsigned e0 = *(const unsigned*)(Al + rA * AST + k0 + cc);
            unsigned e1 = *(const unsigned*)(Al + (rA + 8) * AST + k0 + cc);
            unsigned e2 = *(const unsigned*)(Al + rA * AST + k0 + cc + 8);
            unsigned e3 = *(const unsigned*)(Al + (rA + 8) * AST + k0 + cc + 8);
            #pragma unroll
            for (int gi = 0; gi < 4; gi++) {
                MMA(d[gi][0], d[gi][1], d[gi][2], d[gi][3],
                    a0, a1, a2, a3, bhi[gi][kt][0], bhi[gi][kt][1]);
                MMA(d[gi][0], d[gi][1], d[gi][2], d[gi][3],
                    e0, e1, e2, e3, bhi[gi][kt][0], bhi[gi][kt][1]);
                MMA(d[gi][0], d[gi][1], d[gi][2], d[gi][3],
                    a0, a1, a2, a3, blo[gi][kt][0], blo[gi][kt][1]);
            }
        }
        if (L0) {
            float xA = sm->xs0[t & (NRING - 1)][rA];
            float xB = sm->xs0[t & (NRING - 1)][rA + 8];
            #pragma unroll
            for (int gi = 0; gi < 4; gi++) {
                d[gi][0] += ws[gi][0] * xA; d[gi][1] += ws[gi][1] * xA;
                d[gi][2] += ws[gi][0] * xB; d[gi][3] += ws[gi][1] * xB;
            }
        }
        float hv0, hv1, hv2, hv3;
        { float iv = sigf(d[0][0]), fv = sigf(d[1][0]),
                gv = tanhf_fast(d[2][0]), ov = sigf(d[3][0]);
          c0 = fv * c0 + iv * gv; hv0 = ov * tanhf_fast(c0); }
        { float iv = sigf(d[0][1]), fv = sigf(d[1][1]),
                gv = tanhf_fast(d[2][1]), ov = sigf(d[3][1]);
          c1 = fv * c1 + iv * gv; hv1 = ov * tanhf_fast(c1); }
        { float iv = sigf(d[0][2]), fv = sigf(d[1][2]),
                gv = tanhf_fast(d[2][2]), ov = sigf(d[3][2]);
          c2 = fv * c2 + iv * gv; hv2 = ov * tanhf_fast(c2); }
        { float iv = sigf(d[0][3]), fv = sigf(d[1][3]),
                gv = tanhf_fast(d[2][3]), ov = sigf(d[3][3]);
          c3 = fv * c3 + iv * gv; hv3 = ov * tanhf_fast(c3); }

        const int ns = (t + 1) & 1;
        sts_pair(&sm->Hh[ns][rA][u0],     &sm->Hl[ns][rA][u0],     make_float2(hv0, hv1));
        sts_pair(&sm->Hh[ns][rA + 8][u0], &sm->Hl[ns][rA + 8][u0], make_float2(hv2, hv3));
        *(float2*)(ho + ((size_t)(r0 + rA) * TT + t) * 64 + u0)     = make_float2(hv0, hv1);
        *(float2*)(ho + ((size_t)(r0 + rA + 8) * TT + t) * 64 + u0) = make_float2(hv2, hv3);

        if (!L0) {
            if (t + 6 < TT) {   // STS h_prev[t+6] (loaded last iteration)
                int sl = (t + 6) & (NRING - 1);
                sts_pair(&sm->Xh[sl][srow][su],     &sm->Xl[sl][srow][su],     q0);
                sts_pair(&sm->Xh[sl][srow + 8][su], &sm->Xl[sl][srow + 8][su], q1);
            }
            if (t + 7 < TT) {   // LDG h_prev[t+7]; needs flag >= t+8
                int tgt = t + 8;
                while (fl < tgt) { __nanosleep(64); fl = ld_acquire(pf); }
                q0 = *(const float2*)(hp + pb0 + (size_t)(t + 7) * 64);
                q1 = *(const float2*)(hp + pb1 + (size_t)(t + 7) * 64);
            }
        } else if (tid < RPC) {
            if (t + 6 < TT) sm->xs0[(t + 6) & (NRING - 1)][tid] = qx;
            if (t + 7 < TT) qx = x[(size_t)(r0 + tid) * TT + t + 7];
        }
        bool pub = ((t & 1) == 1);
        if (pub) __threadfence();
        __syncthreads();
        if (pub && tid == 0) st_release(myf, t + 1);
    }
}

extern "C" void kernel_launch(void* const* d_in, const int* in_sizes, int n_in,
                              void* d_out, int out_size)
{
    const float* x    = (const float*)d_in[0];
    const float* wih0 = (const float*)d_in[1];
    const float* wihR = (const float*)d_in[2];
    const float* whh  = (const float*)d_in[3];
    const float* bih  = (const float*)d_in[4];
    const float* bhh  = (const float*)d_in[5];
    const float* W1   = (const float*)d_in[6];
    const float* b1   = (const float*)d_in[7];
    const float* W2   = (const float*)d_in[8];
    const float* b2   = (const float*)d_in[9];
    float* out = (float*)d_out;
    (void)in_sizes; (void)n_in; (void)out_size;

    reset_flags<<<1, 128>>>();
    wavefront<<<GRID_ALL, 256>>>(x, wih0, wihR, whh, bih, bhh,
                                 W1, b1, W2, b2, out);
}

// round 9
// speedup vs baseline: 1.1319x; 1.1319x over previous
#include <cuda_runtime.h>
#include <cuda_fp16.h>

#define BB 256
#define TT 1024
#define HH 64
#define GG 256
#define NL 5
#define CPL 16
#define RPC 16
#define AST 72    // smem half-stride: conflict-free for fragment pattern
#define NRING 8   // h_prev ring depth (skew 7)

__device__ float g_h[NL][(size_t)BB * TT * HH];
__device__ int   g_flags[NL][CPL];

__device__ __forceinline__ float sigf(float x) {
    x = fminf(fmaxf(x, -30.f), 30.f);
    return __fdividef(1.0f, 1.0f + __expf(-x));
}
__device__ __forceinline__ float tanhf_fast(float x) {
    x = fminf(fmaxf(x, -15.f), 15.f);
    float e = __expf(-2.0f * x);
    return __fdividef(1.0f - e, 1.0f + e);
}
__device__ __forceinline__ int ld_acquire(const int* p) {
    int v;
    asm volatile("ld.global.acquire.gpu.b32 %0, [%1];" : "=r"(v) : "l"(p) : "memory");
    return v;
}
__device__ __forceinline__ void st_release(int* p, int v) {
    asm volatile("st.global.release.gpu.b32 [%0], %1;" :: "l"(p), "r"(v) : "memory");
}
__global__ void reset_flags() {
    int i = threadIdx.x;
    if (i < NL * CPL) ((int*)g_flags)[i] = 0;
}

#define MMA(d0, d1, d2, d3, a0, a1, a2, a3, b0, b1)                        \
    asm volatile(                                                          \
        "mma.sync.aligned.m16n8k16.row.col.f32.f16.f16.f32 "               \
        "{%0,%1,%2,%3}, {%4,%5,%6,%7}, {%8,%9}, {%0,%1,%2,%3};"            \
        : "+f"(d0), "+f"(d1), "+f"(d2), "+f"(d3)                           \
        : "r"(a0), "r"(a1), "r"(a2), "r"(a3), "r"(b0), "r"(b1))

__device__ __forceinline__ void split2(float x, __half& hi, __half& lo) {
    hi = __float2half_rn(x);
    lo = __float2half_rn(x - __half2float(hi));
}
__device__ __forceinline__ unsigned packh(__half a, __half b) {
    __half2 h = __halves2half2(a, b);
    return *reinterpret_cast<unsigned*>(&h);
}
__device__ __forceinline__ void sts_pair(__half* dh, __half* dl, float2 v) {
    __half h0, l0, h1, l1;
    split2(v.x, h0, l0); split2(v.y, h1, l1);
    *reinterpret_cast<unsigned*>(dh) = packh(h0, h1);
    *reinterpret_cast<unsigned*>(dl) = packh(l0, l1);
}

// ---------------------------------------------------------------------------
// Tensor-core wavefront: 80 CTAs = 5 layers x 16 chunks x 16 batch rows.
// Per step: gates D[16x256] = [h_own|h_prev][16x128] @ W[128x256] via
// compensated fp16 HMMA; cell update in registers; 1 barrier/step.
// h_prev pipeline skew = 7 steps -> flag acquire is never on critical path.
// ---------------------------------------------------------------------------
__global__ void __launch_bounds__(256, 1)
wavefront(const float* __restrict__ x,     // [B,T]
          const float* __restrict__ wih0,  // [256]
          const float* __restrict__ wihR,  // [4,256,64]
          const float* __restrict__ whh,   // [5,256,64]
          const float* __restrict__ bih,   // [5,256]
          const float* __restrict__ bhh)   // [5,256]
{
    __shared__ __half Hh[2][RPC][AST], Hl[2][RPC][AST];
    __shared__ __half Xh[NRING][RPC][AST], Xl[NRING][RPC][AST];
    __shared__ float xs0[NRING][RPC];

    const int tid = threadIdx.x;
    const int w   = tid >> 5, ln = tid & 31;
    const int li  = blockIdx.x / CPL, ch = blockIdx.x % CPL;
    const int r0  = ch * RPC;
    const bool L0 = (li == 0);
    const int rA = ln >> 2;          // fragment row 0..7
    const int cc = (ln & 3) * 2;     // fragment col pair
    const int u0 = 8 * w + cc;       // unit pair owned by this lane
    const int NKT = L0 ? 4 : 8;

    // ---- weight B-fragments (hi/lo) ----
    unsigned bhi[4][8][2], blo[4][8][2];
    #pragma unroll
    for (int gi = 0; gi < 4; gi++) {
        const int grow = gi * 64 + 8 * w + rA;
        #pragma unroll
        for (int kt = 0; kt < 8; kt++)
            #pragma unroll
            for (int hf = 0; hf < 2; hf++) {
                bhi[gi][kt][hf] = 0; blo[gi][kt][hf] = 0;
                if (kt < NKT) {
                    int kg = ((kt < 4) ? kt * 16 : (kt - 4) * 16) + cc + hf * 8;
                    const float* src = (kt < 4)
                        ? whh  + ((size_t)li * GG + grow) * HH + kg
                        : wihR + ((size_t)(li - 1) * GG + grow) * HH + kg;
                    float2 wv = *reinterpret_cast<const float2*>(src);
                    __half h0, l0, h1, l1;
                    split2(wv.x, h0, l0); split2(wv.y, h1, l1);
                    bhi[gi][kt][hf] = packh(h0, h1);
                    blo[gi][kt][hf] = packh(l0, l1);
                }
            }
    }
    float bs[4][2], ws[4][2];
    #pragma unroll
    for (int gi = 0; gi < 4; gi++)
        #pragma unroll
        for (int e = 0; e < 2; e++) {
            int gu = gi * 64 + u0 + e;
            bs[gi][e] = bih[li * GG + gu] + bhh[li * GG + gu];
            ws[gi][e] = L0 ? wih0[gu] : 0.f;
        }

    for (int i = tid; i < RPC * AST; i += 256) {
        (&Hh[0][0][0])[i] = __float2half(0.f);
        (&Hl[0][0][0])[i] = __float2half(0.f);
    }

    // stager: thread covers rows (srow, srow+8), unit pair su
    const int srow = tid >> 5;
    const int su   = 2 * ln;
    const size_t pb0 = ((size_t)(r0 + srow) * TT) * 64 + su;
    const size_t pb1 = ((size_t)(r0 + srow + 8) * TT) * 64 + su;
    const int* pf = li ? &g_flags[li - 1][ch] : nullptr;
    int* myf = &g_flags[li][ch];
    const float* hp = li ? g_h[li - 1] : nullptr;
    float* ho = g_h[li];
    float2 q0 = make_float2(0.f, 0.f), q1 = make_float2(0.f, 0.f);
    float qx = 0.f;

    // prologue: stage ring slots 0..5, prefetch slot 6 into regs (skew 7)
    if (!L0) {
        while (ld_acquire(pf) < 6) __nanosleep(128);
        #pragma unroll
        for (int s = 0; s < 6; s++) {
            sts_pair(&Xh[s][srow][su],     &Xl[s][srow][su],
                     *(const float2*)(hp + pb0 + (size_t)s * 64));
            sts_pair(&Xh[s][srow + 8][su], &Xl[s][srow + 8][su],
                     *(const float2*)(hp + pb1 + (size_t)s * 64));
        }
        while (ld_acquire(pf) < 7) __nanosleep(128);
        q0 = *(const float2*)(hp + pb0 + 6 * 64);
        q1 = *(const float2*)(hp + pb1 + 6 * 64);
    } else if (tid < RPC) {
        const float* xp = x + (size_t)(r0 + tid) * TT;
        #pragma unroll
        for (int s = 0; s < 6; s++) xs0[s][tid] = xp[s];
        qx = xp[6];
    }
    float c0 = 0.f, c1 = 0.f, c2 = 0.f, c3 = 0.f;
    __syncthreads();

    for (int t = 0; t < TT; ++t) {
        // early flag sample; consumed after the update (latency hidden)
        int fl = 0x7fffffff;
        if (!L0 && t + 7 < TT) fl = ld_acquire(pf);

        float d[4][4];
        #pragma unroll
        for (int gi = 0; gi < 4; gi++) {
            d[gi][0] = bs[gi][0]; d[gi][1] = bs[gi][1];
            d[gi][2] = bs[gi][0]; d[gi][3] = bs[gi][1];
        }
        const __half* HhT = &Hh[t & 1][0][0];
        const __half* HlT = &Hl[t & 1][0][0];
        const __half* XhT = &Xh[t & (NRING - 1)][0][0];
        const __half* XlT = &Xl[t & (NRING - 1)][0][0];
        #pragma unroll
        for (int kt = 0; kt < 8; kt++) {
            if (L0 && kt >= 4) break;
            const __half *Ah, *Al; int k0;
            if (kt < 4) { Ah = HhT; Al = HlT; k0 = kt * 16; }
            else        { Ah = XhT; Al = XlT; k0 = (kt - 4) * 16; }
            unsigned a0 = *(const unsigned*)(Ah + rA * AST + k0 + cc);
            unsigned a1 = *(const unsigned*)(Ah + (rA + 8) * AST + k0 + cc);
            unsigned a2 = *(const unsigned*)(Ah + rA * AST + k0 + cc + 8);
            unsigned a3 = *(const unsigned*)(Ah + (rA + 8) * AST + k0 + cc + 8);
            unsigned e0 = *(const unsigned*)(Al + rA * AST + k0 + cc);
            unsigned e1 = *(const unsigned*)(Al + (rA + 8) * AST + k0 + cc);
            unsigned e2 = *(const unsigned*)(Al + rA * AST + k0 + cc + 8);
            unsigned e3 = *(const unsigned*)(Al + (rA + 8) * AST + k0 + cc + 8);
            #pragma unroll
            for (int gi = 0; gi < 4; gi++) {
                MMA(d[gi][0], d[gi][1], d[gi][2], d[gi][3],
                    a0, a1, a2, a3, bhi[gi][kt][0], bhi[gi][kt][1]);
                MMA(d[gi][0], d[gi][1], d[gi][2], d[gi][3],
                    e0, e1, e2, e3, bhi[gi][kt][0], bhi[gi][kt][1]);
                MMA(d[gi][0], d[gi][1], d[gi][2], d[gi][3],
                    a0, a1, a2, a3, blo[gi][kt][0], blo[gi][kt][1]);
            }
        }
        if (L0) {
            float xA = xs0[t & (NRING - 1)][rA];
            float xB = xs0[t & (NRING - 1)][rA + 8];
            #pragma unroll
            for (int gi = 0; gi < 4; gi++) {
                d[gi][0] += ws[gi][0] * xA; d[gi][1] += ws[gi][1] * xA;
                d[gi][2] += ws[gi][0] * xB; d[gi][3] += ws[gi][1] * xB;
            }
        }
        // in-register LSTM cell update (i,f,g,o = d[0..3])
        float hv0, hv1, hv2, hv3;
        { float iv = sigf(d[0][0]), fv = sigf(d[1][0]),
                gv = tanhf_fast(d[2][0]), ov = sigf(d[3][0]);
          c0 = fv * c0 + iv * gv; hv0 = ov * tanhf_fast(c0); }
        { float iv = sigf(d[0][1]), fv = sigf(d[1][1]),
                gv = tanhf_fast(d[2][1]), ov = sigf(d[3][1]);
          c1 = fv * c1 + iv * gv; hv1 = ov * tanhf_fast(c1); }
        { float iv = sigf(d[0][2]), fv = sigf(d[1][2]),
                gv = tanhf_fast(d[2][2]), ov = sigf(d[3][2]);
          c2 = fv * c2 + iv * gv; hv2 = ov * tanhf_fast(c2); }
        { float iv = sigf(d[0][3]), fv = sigf(d[1][3]),
                gv = tanhf_fast(d[2][3]), ov = sigf(d[3][3]);
          c3 = fv * c3 + iv * gv; hv3 = ov * tanhf_fast(c3); }

        const int ns = (t + 1) & 1;
        sts_pair(&Hh[ns][rA][u0],     &Hl[ns][rA][u0],     make_float2(hv0, hv1));
        sts_pair(&Hh[ns][rA + 8][u0], &Hl[ns][rA + 8][u0], make_float2(hv2, hv3));
        *(float2*)(ho + ((size_t)(r0 + rA) * TT + t) * 64 + u0)     = make_float2(hv0, hv1);
        *(float2*)(ho + ((size_t)(r0 + rA + 8) * TT + t) * 64 + u0) = make_float2(hv2, hv3);

        if (!L0) {
            if (t + 6 < TT) {   // STS h_prev[t+6] (prefetched last iteration)
                int sl = (t + 6) & (NRING - 1);
                sts_pair(&Xh[sl][srow][su],     &Xl[sl][srow][su],     q0);
                sts_pair(&Xh[sl][srow + 8][su], &Xl[sl][srow + 8][su], q1);
            }
            if (t + 7 < TT) {   // LDG h_prev[t+7]; needs flag >= t+8
                int tgt = t + 8;
                while (fl < tgt) { __nanosleep(64); fl = ld_acquire(pf); }
                q0 = *(const float2*)(hp + pb0 + (size_t)(t + 7) * 64);
                q1 = *(const float2*)(hp + pb1 + (size_t)(t + 7) * 64);
            }
        } else if (tid < RPC) {
            if (t + 6 < TT) xs0[(t + 6) & (NRING - 1)][tid] = qx;
            if (t + 7 < TT) qx = x[(size_t)(r0 + tid) * TT + t + 7];
        }
        bool pub = (li < 4) && ((t & 1) == 1);
        if (pub) __threadfence();
        __syncthreads();
        if (pub && tid == 0) st_release(myf, t + 1);
    }
}

// ---------------------------------------------------------------------------
// Head: out = relu(relu(h) @ W1^T + b1) @ W2^T + b2.
// ---------------------------------------------------------------------------
__global__ void __launch_bounds__(256)
fc_kernel(const float* __restrict__ hin, const float* __restrict__ W1,
          const float* __restrict__ b1, const float* __restrict__ W2,
          const float* __restrict__ b2, float* __restrict__ out)
{
    __shared__ float W1T[64 * 64];
    __shared__ float b1s[64], w2s[64];
    __shared__ float hsm[8][64];
    for (int i = threadIdx.x; i < 4096; i += 256) {
        int j = i >> 6, k = i & 63;
        W1T[k * 64 + j] = W1[j * 64 + k];
    }
    if (threadIdx.x < 64) {
        b1s[threadIdx.x] = b1[threadIdx.x];
        w2s[threadIdx.x] = W2[threadIdx.x];
    }
    __syncthreads();
    const float b2v = b2[0];
    const int warp = threadIdx.x >> 5, lane = threadIdx.x & 31;
    for (int p = blockIdx.x * 8 + warp; p < BB * TT; p += gridDim.x * 8) {
        float h0 = fmaxf(hin[(size_t)p * 64 + lane], 0.f);
        float h1 = fmaxf(hin[(size_t)p * 64 + 32 + lane], 0.f);
        hsm[warp][lane] = h0; hsm[warp][lane + 32] = h1;
        __syncwarp();
        float y0 = b1s[lane], y1 = b1s[lane + 32];
        #pragma unroll
        for (int k = 0; k < 64; k++) {
            float hv = hsm[warp][k];
            y0 = fmaf(W1T[k * 64 + lane], hv, y0);
            y1 = fmaf(W1T[k * 64 + lane + 32], hv, y1);
        }
        float part = fmaxf(y0, 0.f) * w2s[lane] + fmaxf(y1, 0.f) * w2s[lane + 32];
        #pragma unroll
        for (int o = 16; o; o >>= 1) part += __shfl_down_sync(~0u, part, o);
        if (!lane) out[p] = part + b2v;
        __syncwarp();
    }
}

extern "C" void kernel_launch(void* const* d_in, const int* in_sizes, int n_in,
                              void* d_out, int out_size)
{
    const float* x    = (const float*)d_in[0];
    const float* wih0 = (const float*)d_in[1];
    const float* wihR = (const float*)d_in[2];
    const float* whh  = (const float*)d_in[3];
    const float* bih  = (const float*)d_in[4];
    const float* bhh  = (const float*)d_in[5];
    const float* W1   = (const float*)d_in[6];
    const float* b1   = (const float*)d_in[7];
    const float* W2   = (const float*)d_in[8];
    const float* b2   = (const float*)d_in[9];
    float* out = (float*)d_out;
    (void)in_sizes; (void)n_in; (void)out_size;

    void* pH = nullptr;
    cudaGetSymbolAddress(&pH, g_h);
    float* h4 = (float*)pH + 4 * (size_t)BB * TT * HH;

    reset_flags<<<1, 128>>>();
    wavefront<<<NL * CPL, 256>>>(x, wih0, wihR, whh, bih, bhh);
    fc_kernel<<<2048, 256>>>(h4, W1, b1, W2, b2, out);
}

// round 10
// speedup vs baseline: 1.2926x; 1.1420x over previous
#include <cuda_runtime.h>
#include <cuda_fp16.h>

#define BB 256
#define TT 1024
#define HH 64
#define GG 256
#define NL 5
#define CPL 16
#define RPC 16
#define AST 72   // smem half-stride: conflict-free for fragment pattern
#define NRING 4  // h_prev ring depth (skew 3 — proven optimum)

__device__ float g_h[NL][(size_t)BB * TT * HH];
__device__ int   g_flags[NL][CPL];

__device__ __forceinline__ float sigf(float x) {
    x = fminf(fmaxf(x, -30.f), 30.f);
    return __fdividef(1.0f, 1.0f + __expf(-x));
}
__device__ __forceinline__ float tanhf_fast(float x) {
    x = fminf(fmaxf(x, -15.f), 15.f);
    float e = __expf(-2.0f * x);
    return __fdividef(1.0f - e, 1.0f + e);
}
__device__ __forceinline__ int ld_acquire(const int* p) {
    int v;
    asm volatile("ld.global.acquire.gpu.b32 %0, [%1];" : "=r"(v) : "l"(p) : "memory");
    return v;
}
__device__ __forceinline__ void st_release(int* p, int v) {
    asm volatile("st.global.release.gpu.b32 [%0], %1;" :: "l"(p), "r"(v) : "memory");
}
__global__ void reset_flags() {
    int i = threadIdx.x;
    if (i < NL * CPL) ((int*)g_flags)[i] = 0;
}

#define MMA(d0, d1, d2, d3, a0, a1, a2, a3, b0, b1)                        \
    asm volatile(                                                          \
        "mma.sync.aligned.m16n8k16.row.col.f32.f16.f16.f32 "               \
        "{%0,%1,%2,%3}, {%4,%5,%6,%7}, {%8,%9}, {%0,%1,%2,%3};"            \
        : "+f"(d0), "+f"(d1), "+f"(d2), "+f"(d3)                           \
        : "r"(a0), "r"(a1), "r"(a2), "r"(a3), "r"(b0), "r"(b1))

__device__ __forceinline__ void split2(float x, __half& hi, __half& lo) {
    hi = __float2half_rn(x);
    lo = __float2half_rn(x - __half2float(hi));
}
__device__ __forceinline__ unsigned packh(__half a, __half b) {
    __half2 h = __halves2half2(a, b);
    return *reinterpret_cast<unsigned*>(&h);
}
__device__ __forceinline__ void sts_pair(__half* dh, __half* dl, float2 v) {
    __half h0, l0, h1, l1;
    split2(v.x, h0, l0); split2(v.y, h1, l1);
    *reinterpret_cast<unsigned*>(dh) = packh(h0, h1);
    *reinterpret_cast<unsigned*>(dl) = packh(l0, l1);
}

// ---------------------------------------------------------------------------
// Tensor-core wavefront: 80 CTAs = 5 layers x 16 chunks x 16 batch rows.
// Per step: gates D[16x256] = [h_own|h_prev][16x128] @ W[128x256] via
// 2-term compensated fp16 HMMA (Ahi·Bhi + Alo·Bhi — weights at fp16-hi,
// h-state fully compensated); cell update in registers; 1 barrier/step.
// ---------------------------------------------------------------------------
__global__ void __launch_bounds__(256, 1)
wavefront(const float* __restrict__ x,     // [B,T]
          const float* __restrict__ wih0,  // [256]
          const float* __restrict__ wihR,  // [4,256,64]
          const float* __restrict__ whh,   // [5,256,64]
          const float* __restrict__ bih,   // [5,256]
          const float* __restrict__ bhh)   // [5,256]
{
    __shared__ __half Hh[2][RPC][AST], Hl[2][RPC][AST];
    __shared__ __half Xh[NRING][RPC][AST], Xl[NRING][RPC][AST];
    __shared__ float xs0[NRING][RPC];

    const int tid = threadIdx.x;
    const int w   = tid >> 5, ln = tid & 31;
    const int li  = blockIdx.x / CPL, ch = blockIdx.x % CPL;
    const int r0  = ch * RPC;
    const bool L0 = (li == 0);
    const int rA = ln >> 2;          // fragment row 0..7
    const int cc = (ln & 3) * 2;     // fragment col pair
    const int u0 = 8 * w + cc;       // unit pair owned by this lane
    const int NKT = L0 ? 4 : 8;

    // ---- weight B-fragments (fp16-hi only) ----
    unsigned bhi[4][8][2];
    #pragma unroll
    for (int gi = 0; gi < 4; gi++) {
        const int grow = gi * 64 + 8 * w + rA;
        #pragma unroll
        for (int kt = 0; kt < 8; kt++)
            #pragma unroll
            for (int hf = 0; hf < 2; hf++) {
                bhi[gi][kt][hf] = 0;
                if (kt < NKT) {
                    int kg = ((kt < 4) ? kt * 16 : (kt - 4) * 16) + cc + hf * 8;
                    const float* src = (kt < 4)
                        ? whh  + ((size_t)li * GG + grow) * HH + kg
                        : wihR + ((size_t)(li - 1) * GG + grow) * HH + kg;
                    float2 wv = *reinterpret_cast<const float2*>(src);
                    bhi[gi][kt][hf] = packh(__float2half_rn(wv.x),
                                            __float2half_rn(wv.y));
                }
            }
    }
    float bs[4][2], ws[4][2];
    #pragma unroll
    for (int gi = 0; gi < 4; gi++)
        #pragma unroll
        for (int e = 0; e < 2; e++) {
            int gu = gi * 64 + u0 + e;
            bs[gi][e] = bih[li * GG + gu] + bhh[li * GG + gu];
            ws[gi][e] = L0 ? wih0[gu] : 0.f;
        }

    for (int i = tid; i < RPC * AST; i += 256) {
        (&Hh[0][0][0])[i] = __float2half(0.f);
        (&Hl[0][0][0])[i] = __float2half(0.f);
    }

    // stager: thread covers rows (srow, srow+8), unit pair su
    const int srow = tid >> 5;
    const int su   = 2 * ln;
    const size_t pb0 = ((size_t)(r0 + srow) * TT) * 64 + su;
    const size_t pb1 = ((size_t)(r0 + srow + 8) * TT) * 64 + su;
    const int* pf = li ? &g_flags[li - 1][ch] : nullptr;
    int* myf = &g_flags[li][ch];
    const float* hp = li ? g_h[li - 1] : nullptr;
    float* ho = g_h[li];
    float2 q0 = make_float2(0.f, 0.f), q1 = make_float2(0.f, 0.f);
    float qx = 0.f;

    // prologue: stage ring slots 0..1, prefetch slot 2 into regs (skew 3)
    if (!L0) {
        while (ld_acquire(pf) < 2) __nanosleep(64);
        #pragma unroll
        for (int s = 0; s < 2; s++) {
            sts_pair(&Xh[s][srow][su],     &Xl[s][srow][su],
                     *(const float2*)(hp + pb0 + (size_t)s * 64));
            sts_pair(&Xh[s][srow + 8][su], &Xl[s][srow + 8][su],
                     *(const float2*)(hp + pb1 + (size_t)s * 64));
        }
        while (ld_acquire(pf) < 3) __nanosleep(64);
        q0 = *(const float2*)(hp + pb0 + 2 * 64);
        q1 = *(const float2*)(hp + pb1 + 2 * 64);
    } else if (tid < RPC) {
        const float* xp = x + (size_t)(r0 + tid) * TT;
        xs0[0][tid] = xp[0];
        xs0[1][tid] = xp[1];
        qx = xp[2];
    }
    float c0 = 0.f, c1 = 0.f, c2 = 0.f, c3 = 0.f;
    __syncthreads();

    for (int t = 0; t < TT; ++t) {
        float d[4][4];
        #pragma unroll
        for (int gi = 0; gi < 4; gi++) {
            d[gi][0] = bs[gi][0]; d[gi][1] = bs[gi][1];
            d[gi][2] = bs[gi][0]; d[gi][3] = bs[gi][1];
        }
        const __half* HhT = &Hh[t & 1][0][0];
        const __half* HlT = &Hl[t & 1][0][0];
        const __half* XhT = &Xh[t & (NRING - 1)][0][0];
        const __half* XlT = &Xl[t & (NRING - 1)][0][0];
        #pragma unroll
        for (int kt = 0; kt < 8; kt++) {
            if (L0 && kt >= 4) break;
            const __half *Ah, *Al; int k0;
            if (kt < 4) { Ah = HhT; Al = HlT; k0 = kt * 16; }
            else        { Ah = XhT; Al = XlT; k0 = (kt - 4) * 16; }
            unsigned a0 = *(const unsigned*)(Ah + rA * AST + k0 + cc);
            unsigned a1 = *(const unsigned*)(Ah + (rA + 8) * AST + k0 + cc);
            unsigned a2 = *(const unsigned*)(Ah + rA * AST + k0 + cc + 8);
            unsigned a3 = *(const unsigned*)(Ah + (rA + 8) * AST + k0 + cc + 8);
            unsigned e0 = *(const unsigned*)(Al + rA * AST + k0 + cc);
            unsigned e1 = *(const unsigned*)(Al + (rA + 8) * AST + k0 + cc);
            unsigned e2 = *(const unsigned*)(Al + rA * AST + k0 + cc + 8);
            unsigned e3 = *(const unsigned*)(Al + (rA + 8) * AST + k0 + cc + 8);
            #pragma unroll
            for (int gi = 0; gi < 4; gi++) {
                MMA(d[gi][0], d[gi][1], d[gi][2], d[gi][3],
                    a0, a1, a2, a3, bhi[gi][kt][0], bhi[gi][kt][1]);
                MMA(d[gi][0], d[gi][1], d[gi][2], d[gi][3],
                    e0, e1, e2, e3, bhi[gi][kt][0], bhi[gi][kt][1]);
            }
        }
        if (L0) {
            float xA = xs0[t & (NRING - 1)][rA];
            float xB = xs0[t & (NRING - 1)][rA + 8];
            #pragma unroll
            for (int gi = 0; gi < 4; gi++) {
                d[gi][0] += ws[gi][0] * xA; d[gi][1] += ws[gi][1] * xA;
                d[gi][2] += ws[gi][0] * xB; d[gi][3] += ws[gi][1] * xB;
            }
        }
        // in-register LSTM cell update (i,f,g,o = d[0..3])
        float hv0, hv1, hv2, hv3;
        { float iv = sigf(d[0][0]), fv = sigf(d[1][0]),
                gv = tanhf_fast(d[2][0]), ov = sigf(d[3][0]);
          c0 = fv * c0 + iv * gv; hv0 = ov * tanhf_fast(c0); }
        { float iv = sigf(d[0][1]), fv = sigf(d[1][1]),
                gv = tanhf_fast(d[2][1]), ov = sigf(d[3][1]);
          c1 = fv * c1 + iv * gv; hv1 = ov * tanhf_fast(c1); }
        { float iv = sigf(d[0][2]), fv = sigf(d[1][2]),
                gv = tanhf_fast(d[2][2]), ov = sigf(d[3][2]);
          c2 = fv * c2 + iv * gv; hv2 = ov * tanhf_fast(c2); }
        { float iv = sigf(d[0][3]), fv = sigf(d[1][3]),
                gv = tanhf_fast(d[2][3]), ov = sigf(d[3][3]);
          c3 = fv * c3 + iv * gv; hv3 = ov * tanhf_fast(c3); }

        const int ns = (t + 1) & 1;
        sts_pair(&Hh[ns][rA][u0],     &Hl[ns][rA][u0],     make_float2(hv0, hv1));
        sts_pair(&Hh[ns][rA + 8][u0], &Hl[ns][rA + 8][u0], make_float2(hv2, hv3));
        *(float2*)(ho + ((size_t)(r0 + rA) * TT + t) * 64 + u0)     = make_float2(hv0, hv1);
        *(float2*)(ho + ((size_t)(r0 + rA + 8) * TT + t) * 64 + u0) = make_float2(hv2, hv3);

        if (!L0) {
            if (t + 2 < TT) {   // STS h_prev[t+2] (prefetched last iteration)
                int sl = (t + 2) & (NRING - 1);
                sts_pair(&Xh[sl][srow][su],     &Xl[sl][srow][su],     q0);
                sts_pair(&Xh[sl][srow + 8][su], &Xl[sl][srow + 8][su], q1);
            }
            if (t + 3 < TT) {   // LDG h_prev[t+3]; needs flag >= t+4
                int fl = ld_acquire(pf);
                while (fl < t + 4) { __nanosleep(64); fl = ld_acquire(pf); }
                q0 = *(const float2*)(hp + pb0 + (size_t)(t + 3) * 64);
                q1 = *(const float2*)(hp + pb1 + (size_t)(t + 3) * 64);
            }
        } else if (tid < RPC) {
            if (t + 2 < TT) xs0[(t + 2) & (NRING - 1)][tid] = qx;
            if (t + 3 < TT) qx = x[(size_t)(r0 + tid) * TT + t + 3];
        }
        bool pub = (li < 4) && ((t & 1) == 1);
        if (pub) __threadfence();
        __syncthreads();
        if (pub && tid == 0) st_release(myf, t + 1);
    }
}

// ---------------------------------------------------------------------------
// Head: out = relu(relu(h) @ W1^T + b1) @ W2^T + b2.
// ---------------------------------------------------------------------------
__global__ void __launch_bounds__(256)
fc_kernel(const float* __restrict__ hin, const float* __restrict__ W1,
          const float* __restrict__ b1, const float* __restrict__ W2,
          const float* __restrict__ b2, float* __restrict__ out)
{
    __shared__ float W1T[64 * 64];
    __shared__ float b1s[64], w2s[64];
    __shared__ float hsm[8][64];
    for (int i = threadIdx.x; i < 4096; i += 256) {
        int j = i >> 6, k = i & 63;
        W1T[k * 64 + j] = W1[j * 64 + k];
    }
    if (threadIdx.x < 64) {
        b1s[threadIdx.x] = b1[threadIdx.x];
        w2s[threadIdx.x] = W2[threadIdx.x];
    }
    __syncthreads();
    const float b2v = b2[0];
    const int warp = threadIdx.x >> 5, lane = threadIdx.x & 31;
    for (int p = blockIdx.x * 8 + warp; p < BB * TT; p += gridDim.x * 8) {
        float h0 = fmaxf(hin[(size_t)p * 64 + lane], 0.f);
        float h1 = fmaxf(hin[(size_t)p * 64 + 32 + lane], 0.f);
        hsm[warp][lane] = h0; hsm[warp][lane + 32] = h1;
        __syncwarp();
        float y0 = b1s[lane], y1 = b1s[lane + 32];
        #pragma unroll
        for (int k = 0; k < 64; k++) {
            float hv = hsm[warp][k];
            y0 = fmaf(W1T[k * 64 + lane], hv, y0);
            y1 = fmaf(W1T[k * 64 + lane + 32], hv, y1);
        }
        float part = fmaxf(y0, 0.f) * w2s[lane] + fmaxf(y1, 0.f) * w2s[lane + 32];
        #pragma unroll
        for (int o = 16; o; o >>= 1) part += __shfl_down_sync(~0u, part, o);
        if (!lane) out[p] = part + b2v;
        __syncwarp();
    }
}

extern "C" void kernel_launch(void* const* d_in, const int* in_sizes, int n_in,
                              void* d_out, int out_size)
{
    const float* x    = (const float*)d_in[0];
    const float* wih0 = (const float*)d_in[1];
    const float* wihR = (const float*)d_in[2];
    const float* whh  = (const float*)d_in[3];
    const float* bih  = (const float*)d_in[4];
    const float* bhh  = (const float*)d_in[5];
    const float* W1   = (const float*)d_in[6];
    const float* b1   = (const float*)d_in[7];
    const float* W2   = (const float*)d_in[8];
    const float* b2   = (const float*)d_in[9];
    float* out = (float*)d_out;
    (void)in_sizes; (void)n_in; (void)out_size;

    void* pH = nullptr;
    cudaGetSymbolAddress(&pH, g_h);
    float* h4 = (float*)pH + 4 * (size_t)BB * TT * HH;

    reset_flags<<<1, 128>>>();
    wavefront<<<NL * CPL, 256>>>(x, wih0, wihR, whh, bih, bhh);
    fc_kernel<<<2048, 256>>>(h4, W1, b1, W2, b2, out);
}

// round 11
// speedup vs baseline: 1.4338x; 1.1093x over previous
#include <cuda_runtime.h>
#include <cuda_fp16.h>

#define BB 256
#define TT 1024
#define HH 64
#define GG 256
#define NL 5
#define CPL 16
#define RPC 16
#define AST 72   // smem half-stride: conflict-free for fragment pattern
#define NRING 4  // h_prev ring depth (skew 3)

__device__ float g_h[NL][(size_t)BB * TT * HH];
__device__ int   g_flags[NL][CPL];

__device__ __forceinline__ float sigf(float x) {
    x = fminf(fmaxf(x, -30.f), 30.f);
    return __fdividef(1.0f, 1.0f + __expf(-x));
}
__device__ __forceinline__ float tanhf_fast(float x) {
    x = fminf(fmaxf(x, -15.f), 15.f);
    float e = __expf(-2.0f * x);
    return __fdividef(1.0f - e, 1.0f + e);
}
__device__ __forceinline__ int ld_acquire(const int* p) {
    int v;
    asm volatile("ld.global.acquire.gpu.b32 %0, [%1];" : "=r"(v) : "l"(p) : "memory");
    return v;
}
__device__ __forceinline__ void st_release(int* p, int v) {
    asm volatile("st.global.release.gpu.b32 [%0], %1;" :: "l"(p), "r"(v) : "memory");
}
__global__ void reset_flags() {
    int i = threadIdx.x;
    if (i < NL * CPL) ((int*)g_flags)[i] = 0;
}

#define MMA(d0, d1, d2, d3, a0, a1, a2, a3, b0, b1)                        \
    asm volatile(                                                          \
        "mma.sync.aligned.m16n8k16.row.col.f32.f16.f16.f32 "               \
        "{%0,%1,%2,%3}, {%4,%5,%6,%7}, {%8,%9}, {%0,%1,%2,%3};"            \
        : "+f"(d0), "+f"(d1), "+f"(d2), "+f"(d3)                           \
        : "r"(a0), "r"(a1), "r"(a2), "r"(a3), "r"(b0), "r"(b1))

__device__ __forceinline__ void split2(float x, __half& hi, __half& lo) {
    hi = __float2half_rn(x);
    lo = __float2half_rn(x - __half2float(hi));
}
__device__ __forceinline__ unsigned packh(__half a, __half b) {
    __half2 h = __halves2half2(a, b);
    return *reinterpret_cast<unsigned*>(&h);
}
__device__ __forceinline__ void sts_pair(__half* dh, __half* dl, float2 v) {
    __half h0, l0, h1, l1;
    split2(v.x, h0, l0); split2(v.y, h1, l1);
    *reinterpret_cast<unsigned*>(dh) = packh(h0, h1);
    *reinterpret_cast<unsigned*>(dl) = packh(l0, l1);
}

// ---------------------------------------------------------------------------
// Tensor-core wavefront: 80 CTAs = 5 layers x 16 chunks x 16 batch rows.
// Gates: D[16x256] = [h_own|h_prev][16x128] @ W[128x256], fp16 HMMA with
// h-state hi/lo compensation (2-term). Critical-path engineering:
//  - h-part accumulators split in 2 independent chains (depth 4 each)
//  - x-part (h_prev @ W_ih) computed for step t+1 BEFORE the barrier,
//    so post-barrier work is only the h-part + activations.
// ---------------------------------------------------------------------------
__global__ void __launch_bounds__(256, 1)
wavefront(const float* __restrict__ x,     // [B,T]
          const float* __restrict__ wih0,  // [256]
          const float* __restrict__ wihR,  // [4,256,64]
          const float* __restrict__ whh,   // [5,256,64]
          const float* __restrict__ bih,   // [5,256]
          const float* __restrict__ bhh)   // [5,256]
{
    __shared__ __half Hh[2][RPC][AST], Hl[2][RPC][AST];
    __shared__ __half Xh[NRING][RPC][AST], Xl[NRING][RPC][AST];
    __shared__ float xs0[NRING][RPC];

    const int tid = threadIdx.x;
    const int w   = tid >> 5, ln = tid & 31;
    const int li  = blockIdx.x / CPL, ch = blockIdx.x % CPL;
    const int r0  = ch * RPC;
    const bool L0 = (li == 0);
    const int rA = ln >> 2;          // fragment row 0..7
    const int cc = (ln & 3) * 2;     // fragment col pair
    const int u0 = 8 * w + cc;       // unit pair owned by this lane
    const int NKT = L0 ? 4 : 8;

    // ---- weight B-fragments (fp16-hi; kt 0-3 = W_hh, kt 4-7 = W_ih) ----
    unsigned bhi[4][8][2];
    #pragma unroll
    for (int gi = 0; gi < 4; gi++) {
        const int grow = gi * 64 + 8 * w + rA;
        #pragma unroll
        for (int kt = 0; kt < 8; kt++)
            #pragma unroll
            for (int hf = 0; hf < 2; hf++) {
                bhi[gi][kt][hf] = 0;
                if (kt < NKT) {
                    int kg = ((kt < 4) ? kt * 16 : (kt - 4) * 16) + cc + hf * 8;
                    const float* src = (kt < 4)
                        ? whh  + ((size_t)li * GG + grow) * HH + kg
                        : wihR + ((size_t)(li - 1) * GG + grow) * HH + kg;
                    float2 wv = *reinterpret_cast<const float2*>(src);
                    bhi[gi][kt][hf] = packh(__float2half_rn(wv.x),
                                            __float2half_rn(wv.y));
                }
            }
    }
    float bs[4][2], ws[4][2];
    #pragma unroll
    for (int gi = 0; gi < 4; gi++)
        #pragma unroll
        for (int e = 0; e < 2; e++) {
            int gu = gi * 64 + u0 + e;
            bs[gi][e] = bih[li * GG + gu] + bhh[li * GG + gu];
            ws[gi][e] = L0 ? wih0[gu] : 0.f;
        }

    for (int i = tid; i < RPC * AST; i += 256) {
        (&Hh[0][0][0])[i] = __float2half(0.f);
        (&Hl[0][0][0])[i] = __float2half(0.f);
    }

    // stager: thread covers rows (srow, srow+8), unit pair su
    const int srow = tid >> 5;
    const int su   = 2 * ln;
    const size_t pb0 = ((size_t)(r0 + srow) * TT) * 64 + su;
    const size_t pb1 = ((size_t)(r0 + srow + 8) * TT) * 64 + su;
    const int* pf = li ? &g_flags[li - 1][ch] : nullptr;
    int* myf = &g_flags[li][ch];
    const float* hp = li ? g_h[li - 1] : nullptr;
    float* ho = g_h[li];
    float2 q0 = make_float2(0.f, 0.f), q1 = make_float2(0.f, 0.f);
    float qx = 0.f;

    // prologue: stage ring slots 0..1, prefetch slot 2 into regs (skew 3)
    if (!L0) {
        while (ld_acquire(pf) < 2) __nanosleep(64);
        #pragma unroll
        for (int s = 0; s < 2; s++) {
            sts_pair(&Xh[s][srow][su],     &Xl[s][srow][su],
                     *(const float2*)(hp + pb0 + (size_t)s * 64));
            sts_pair(&Xh[s][srow + 8][su], &Xl[s][srow + 8][su],
                     *(const float2*)(hp + pb1 + (size_t)s * 64));
        }
        while (ld_acquire(pf) < 3) __nanosleep(64);
        q0 = *(const float2*)(hp + pb0 + 2 * 64);
        q1 = *(const float2*)(hp + pb1 + 2 * 64);
    } else if (tid < RPC) {
        const float* xp = x + (size_t)(r0 + tid) * TT;
        xs0[0][tid] = xp[0];
        xs0[1][tid] = xp[1];
        qx = xp[2];
    }
    float c0 = 0.f, c1 = 0.f, c2 = 0.f, c3 = 0.f;
    __syncthreads();

    // dX = bias + x-contribution for the UPCOMING step (t), computed from
    // ring slot t. Prologue computes it for t=0.
    float dX[4][4];
    {
        #pragma unroll
        for (int gi = 0; gi < 4; gi++) {
            dX[gi][0] = bs[gi][0]; dX[gi][1] = bs[gi][1];
            dX[gi][2] = bs[gi][0]; dX[gi][3] = bs[gi][1];
        }
        if (!L0) {
            const __half* XhN = &Xh[0][0][0];
            const __half* XlN = &Xl[0][0][0];
            #pragma unroll
            for (int kt = 0; kt < 4; kt++) {
                int k0 = kt * 16;
                unsigned a0 = *(const unsigned*)(XhN + rA * AST + k0 + cc);
                unsigned a1 = *(const unsigned*)(XhN + (rA + 8) * AST + k0 + cc);
                unsigned a2 = *(const unsigned*)(XhN + rA * AST + k0 + cc + 8);
                unsigned a3 = *(const unsigned*)(XhN + (rA + 8) * AST + k0 + cc + 8);
                unsigned e0 = *(const unsigned*)(XlN + rA * AST + k0 + cc);
                unsigned e1 = *(const unsigned*)(XlN + (rA + 8) * AST + k0 + cc);
                unsigned e2 = *(const unsigned*)(XlN + rA * AST + k0 + cc + 8);
                unsigned e3 = *(const unsigned*)(XlN + (rA + 8) * AST + k0 + cc + 8);
                #pragma unroll
                for (int gi = 0; gi < 4; gi++) {
                    MMA(dX[gi][0], dX[gi][1], dX[gi][2], dX[gi][3],
                        a0, a1, a2, a3, bhi[gi][kt + 4][0], bhi[gi][kt + 4][1]);
                    MMA(dX[gi][0], dX[gi][1], dX[gi][2], dX[gi][3],
                        e0, e1, e2, e3, bhi[gi][kt + 4][0], bhi[gi][kt + 4][1]);
                }
            }
        } else {
            float xA = xs0[0][rA], xB = xs0[0][rA + 8];
            #pragma unroll
            for (int gi = 0; gi < 4; gi++) {
                dX[gi][0] += ws[gi][0] * xA; dX[gi][1] += ws[gi][1] * xA;
                dX[gi][2] += ws[gi][0] * xB; dX[gi][3] += ws[gi][1] * xB;
            }
        }
    }

    for (int t = 0; t < TT; ++t) {
        // ---- post-barrier critical path: h-part (2 chains, depth 4) ----
        float dM[4][4], dS[4][4];
        #pragma unroll
        for (int gi = 0; gi < 4; gi++)
            #pragma unroll
            for (int e = 0; e < 4; e++) { dM[gi][e] = dX[gi][e]; dS[gi][e] = 0.f; }

        const __half* HhT = &Hh[t & 1][0][0];
        const __half* HlT = &Hl[t & 1][0][0];
        #pragma unroll
        for (int kt = 0; kt < 4; kt++) {
            int k0 = kt * 16;
            unsigned a0 = *(const unsigned*)(HhT + rA * AST + k0 + cc);
            unsigned a1 = *(const unsigned*)(HhT + (rA + 8) * AST + k0 + cc);
            unsigned a2 = *(const unsigned*)(HhT + rA * AST + k0 + cc + 8);
            unsigned a3 = *(const unsigned*)(HhT + (rA + 8) * AST + k0 + cc + 8);
            unsigned e0 = *(const unsigned*)(HlT + rA * AST + k0 + cc);
            unsigned e1 = *(const unsigned*)(HlT + (rA + 8) * AST + k0 + cc);
            unsigned e2 = *(const unsigned*)(HlT + rA * AST + k0 + cc + 8);
            unsigned e3 = *(const unsigned*)(HlT + (rA + 8) * AST + k0 + cc + 8);
            #pragma unroll
            for (int gi = 0; gi < 4; gi++) {
                MMA(dM[gi][0], dM[gi][1], dM[gi][2], dM[gi][3],
                    a0, a1, a2, a3, bhi[gi][kt][0], bhi[gi][kt][1]);
                MMA(dS[gi][0], dS[gi][1], dS[gi][2], dS[gi][3],
                    e0, e1, e2, e3, bhi[gi][kt][0], bhi[gi][kt][1]);
            }
        }

        // ---- in-register LSTM cell update ----
        float hv0, hv1, hv2, hv3;
        { float iv = sigf(dM[0][0] + dS[0][0]), fv = sigf(dM[1][0] + dS[1][0]),
                gv = tanhf_fast(dM[2][0] + dS[2][0]), ov = sigf(dM[3][0] + dS[3][0]);
          c0 = fv * c0 + iv * gv; hv0 = ov * tanhf_fast(c0); }
        { float iv = sigf(dM[0][1] + dS[0][1]), fv = sigf(dM[1][1] + dS[1][1]),
                gv = tanhf_fast(dM[2][1] + dS[2][1]), ov = sigf(dM[3][1] + dS[3][1]);
          c1 = fv * c1 + iv * gv; hv1 = ov * tanhf_fast(c1); }
        { float iv = sigf(dM[0][2] + dS[0][2]), fv = sigf(dM[1][2] + dS[1][2]),
                gv = tanhf_fast(dM[2][2] + dS[2][2]), ov = sigf(dM[3][2] + dS[3][2]);
          c2 = fv * c2 + iv * gv; hv2 = ov * tanhf_fast(c2); }
        { float iv = sigf(dM[0][3] + dS[0][3]), fv = sigf(dM[1][3] + dS[1][3]),
                gv = tanhf_fast(dM[2][3] + dS[2][3]), ov = sigf(dM[3][3] + dS[3][3]);
          c3 = fv * c3 + iv * gv; hv3 = ov * tanhf_fast(c3); }

        const int ns = (t + 1) & 1;
        sts_pair(&Hh[ns][rA][u0],     &Hl[ns][rA][u0],     make_float2(hv0, hv1));
        sts_pair(&Hh[ns][rA + 8][u0], &Hl[ns][rA + 8][u0], make_float2(hv2, hv3));
        *(float2*)(ho + ((size_t)(r0 + rA) * TT + t) * 64 + u0)     = make_float2(hv0, hv1);
        *(float2*)(ho + ((size_t)(r0 + rA + 8) * TT + t) * 64 + u0) = make_float2(hv2, hv3);

        // ---- pre-barrier: x-part for step t+1 (ring slot t+1, staged at t-1) ----
        if (t + 1 < TT) {
            #pragma unroll
            for (int gi = 0; gi < 4; gi++) {
                dX[gi][0] = bs[gi][0]; dX[gi][1] = bs[gi][1];
                dX[gi][2] = bs[gi][0]; dX[gi][3] = bs[gi][1];
            }
            if (!L0) {
                const __half* XhN = &Xh[(t + 1) & (NRING - 1)][0][0];
                const __half* XlN = &Xl[(t + 1) & (NRING - 1)][0][0];
                #pragma unroll
                for (int kt = 0; kt < 4; kt++) {
                    int k0 = kt * 16;
                    unsigned a0 = *(const unsigned*)(XhN + rA * AST + k0 + cc);
                    unsigned a1 = *(const unsigned*)(XhN + (rA + 8) * AST + k0 + cc);
                    unsigned a2 = *(const unsigned*)(XhN + rA * AST + k0 + cc + 8);
                    unsigned a3 = *(const unsigned*)(XhN + (rA + 8) * AST + k0 + cc + 8);
                    unsigned e0 = *(const unsigned*)(XlN + rA * AST + k0 + cc);
                    unsigned e1 = *(const unsigned*)(XlN + (rA + 8) * AST + k0 + cc);
                    unsigned e2 = *(const unsigned*)(XlN + rA * AST + k0 + cc + 8);
                    unsigned e3 = *(const unsigned*)(XlN + (rA + 8) * AST + k0 + cc + 8);
                    #pragma unroll
                    for (int gi = 0; gi < 4; gi++) {
                        MMA(dX[gi][0], dX[gi][1], dX[gi][2], dX[gi][3],
                            a0, a1, a2, a3, bhi[gi][kt + 4][0], bhi[gi][kt + 4][1]);
                        MMA(dX[gi][0], dX[gi][1], dX[gi][2], dX[gi][3],
                            e0, e1, e2, e3, bhi[gi][kt + 4][0], bhi[gi][kt + 4][1]);
                    }
                }
            } else {
                float xA = xs0[(t + 1) & (NRING - 1)][rA];
                float xB = xs0[(t + 1) & (NRING - 1)][rA + 8];
                #pragma unroll
                for (int gi = 0; gi < 4; gi++) {
                    dX[gi][0] += ws[gi][0] * xA; dX[gi][1] += ws[gi][1] * xA;
                    dX[gi][2] += ws[gi][0] * xB; dX[gi][3] += ws[gi][1] * xB;
                }
            }
        }

        // ---- staging: STS slot t+2 (prefetched), LDG slot t+3 ----
        if (!L0) {
            if (t + 2 < TT) {
                int sl = (t + 2) & (NRING - 1);
                sts_pair(&Xh[sl][srow][su],     &Xl[sl][srow][su],     q0);
                sts_pair(&Xh[sl][srow + 8][su], &Xl[sl][srow + 8][su], q1);
            }
            if (t + 3 < TT) {
                int fl = ld_acquire(pf);
                while (fl < t + 4) { __nanosleep(64); fl = ld_acquire(pf); }
                q0 = *(const float2*)(hp + pb0 + (size_t)(t + 3) * 64);
                q1 = *(const float2*)(hp + pb1 + (size_t)(t + 3) * 64);
            }
        } else if (tid < RPC) {
            if (t + 2 < TT) xs0[(t + 2) & (NRING - 1)][tid] = qx;
            if (t + 3 < TT) qx = x[(size_t)(r0 + tid) * TT + t + 3];
        }
        bool pub = (li < 4) && ((t & 1) == 1);
        if (pub) __threadfence();
        __syncthreads();
        if (pub && tid == 0) st_release(myf, t + 1);
    }
}

// ---------------------------------------------------------------------------
// Head: out = relu(relu(h) @ W1^T + b1) @ W2^T + b2.
// ---------------------------------------------------------------------------
__global__ void __launch_bounds__(256)
fc_kernel(const float* __restrict__ hin, const float* __restrict__ W1,
          const float* __restrict__ b1, const float* __restrict__ W2,
          const float* __restrict__ b2, float* __restrict__ out)
{
    __shared__ float W1T[64 * 64];
    __shared__ float b1s[64], w2s[64];
    __shared__ float hsm[8][64];
    for (int i = threadIdx.x; i < 4096; i += 256) {
        int j = i >> 6, k = i & 63;
        W1T[k * 64 + j] = W1[j * 64 + k];
    }
    if (threadIdx.x < 64) {
        b1s[threadIdx.x] = b1[threadIdx.x];
        w2s[threadIdx.x] = W2[threadIdx.x];
    }
    __syncthreads();
    const float b2v = b2[0];
    const int warp = threadIdx.x >> 5, lane = threadIdx.x & 31;
    for (int p = blockIdx.x * 8 + warp; p < BB * TT; p += gridDim.x * 8) {
        float h0 = fmaxf(hin[(size_t)p * 64 + lane], 0.f);
        float h1 = fmaxf(hin[(size_t)p * 64 + 32 + lane], 0.f);
        hsm[warp][lane] = h0; hsm[warp][lane + 32] = h1;
        __syncwarp();
        float y0 = b1s[lane], y1 = b1s[lane + 32];
        #pragma unroll
        for (int k = 0; k < 64; k++) {
            float hv = hsm[warp][k];
            y0 = fmaf(W1T[k * 64 + lane], hv, y0);
            y1 = fmaf(W1T[k * 64 + lane + 32], hv, y1);
        }
        float part = fmaxf(y0, 0.f) * w2s[lane] + fmaxf(y1, 0.f) * w2s[lane + 32];
        #pragma unroll
        for (int o = 16; o; o >>= 1) part += __shfl_down_sync(~0u, part, o);
        if (!lane) out[p] = part + b2v;
        __syncwarp();
    }
}

extern "C" void kernel_launch(void* const* d_in, const int* in_sizes, int n_in,
                              void* d_out, int out_size)
{
    const float* x    = (const float*)d_in[0];
    const float* wih0 = (const float*)d_in[1];
    const float* wihR = (const float*)d_in[2];
    const float* whh  = (const float*)d_in[3];
    const float* bih  = (const float*)d_in[4];
    const float* bhh  = (const float*)d_in[5];
    const float* W1   = (const float*)d_in[6];
    const float* b1   = (const float*)d_in[7];
    const float* W2   = (const float*)d_in[8];
    const float* b2   = (const float*)d_in[9];
    float* out = (float*)d_out;
    (void)in_sizes; (void)n_in; (void)out_size;

    void* pH = nullptr;
    cudaGetSymbolAddress(&pH, g_h);
    float* h4 = (float*)pH + 4 * (size_t)BB * TT * HH;

    reset_flags<<<1, 128>>>();
    wavefront<<<NL * CPL, 256>>>(x, wih0, wihR, whh, bih, bhh);
    fc_kernel<<<2048, 256>>>(h4, W1, b1, W2, b2, out);
}

// round 12
// speedup vs baseline: 1.6517x; 1.1519x over previous
#include <cuda_runtime.h>
#include <cuda_fp16.h>

#define BB 256
#define TT 1024
#define HH 64
#define GG 256
#define NL 5
#define CPL 16
#define RPC 16
#define AST 72   // smem half-stride: conflict-free for fragment pattern
#define NRING 4  // h_prev ring depth (skew 3)

__device__ float g_h[NL][(size_t)BB * TT * HH];
__device__ int   g_flags[NL][CPL];

// Single-MUFU activations (sm_75+ tanh.approx).
__device__ __forceinline__ float tanh_fast(float x) {
    float y;
    asm("tanh.approx.f32 %0, %1;" : "=f"(y) : "f"(x));
    return y;
}
__device__ __forceinline__ float sig_fast(float x) {
    return fmaf(0.5f, tanh_fast(0.5f * x), 0.5f);
}

__device__ __forceinline__ int ld_acquire(const int* p) {
    int v;
    asm volatile("ld.global.acquire.gpu.b32 %0, [%1];" : "=r"(v) : "l"(p) : "memory");
    return v;
}
__device__ __forceinline__ void st_release(int* p, int v) {
    asm volatile("st.global.release.gpu.b32 [%0], %1;" :: "l"(p), "r"(v) : "memory");
}
__global__ void reset_flags() {
    int i = threadIdx.x;
    if (i < NL * CPL) ((int*)g_flags)[i] = 0;
}

#define MMA(d0, d1, d2, d3, a0, a1, a2, a3, b0, b1)                        \
    asm volatile(                                                          \
        "mma.sync.aligned.m16n8k16.row.col.f32.f16.f16.f32 "               \
        "{%0,%1,%2,%3}, {%4,%5,%6,%7}, {%8,%9}, {%0,%1,%2,%3};"            \
        : "+f"(d0), "+f"(d1), "+f"(d2), "+f"(d3)                           \
        : "r"(a0), "r"(a1), "r"(a2), "r"(a3), "r"(b0), "r"(b1))

__device__ __forceinline__ void split2(float x, __half& hi, __half& lo) {
    hi = __float2half_rn(x);
    lo = __float2half_rn(x - __half2float(hi));
}
__device__ __forceinline__ unsigned packh(__half a, __half b) {
    __half2 h = __halves2half2(a, b);
    return *reinterpret_cast<unsigned*>(&h);
}
__device__ __forceinline__ void sts_pair(__half* dh, __half* dl, float2 v) {
    __half h0, l0, h1, l1;
    split2(v.x, h0, l0); split2(v.y, h1, l1);
    *reinterpret_cast<unsigned*>(dh) = packh(h0, h1);
    *reinterpret_cast<unsigned*>(dl) = packh(l0, l1);
}

// ---------------------------------------------------------------------------
// Tensor-core wavefront: 80 CTAs = 5 layers x 16 chunks x 16 batch rows.
// Gates via fp16 HMMA with h-state hi/lo compensation. Critical path:
// post-barrier = h-part (2 indep chains, depth 4) + single-MUFU activations;
// x-part for t+1 hoisted pre-barrier. Publish via st.release (no fence —
// release store after __syncthreads orders all CTA writes).
// ---------------------------------------------------------------------------
__global__ void __launch_bounds__(256, 1)
wavefront(const float* __restrict__ x,     // [B,T]
          const float* __restrict__ wih0,  // [256]
          const float* __restrict__ wihR,  // [4,256,64]
          const float* __restrict__ whh,   // [5,256,64]
          const float* __restrict__ bih,   // [5,256]
          const float* __restrict__ bhh)   // [5,256]
{
    __shared__ __half Hh[2][RPC][AST], Hl[2][RPC][AST];
    __shared__ __half Xh[NRING][RPC][AST], Xl[NRING][RPC][AST];
    __shared__ float xs0[NRING][RPC];

    const int tid = threadIdx.x;
    const int w   = tid >> 5, ln = tid & 31;
    const int li  = blockIdx.x / CPL, ch = blockIdx.x % CPL;
    const int r0  = ch * RPC;
    const bool L0 = (li == 0);
    const int rA = ln >> 2;          // fragment row 0..7
    const int cc = (ln & 3) * 2;     // fragment col pair
    const int u0 = 8 * w + cc;       // unit pair owned by this lane
    const int NKT = L0 ? 4 : 8;

    // ---- weight B-fragments (fp16-hi; kt 0-3 = W_hh, kt 4-7 = W_ih) ----
    unsigned bhi[4][8][2];
    #pragma unroll
    for (int gi = 0; gi < 4; gi++) {
        const int grow = gi * 64 + 8 * w + rA;
        #pragma unroll
        for (int kt = 0; kt < 8; kt++)
            #pragma unroll
            for (int hf = 0; hf < 2; hf++) {
                bhi[gi][kt][hf] = 0;
                if (kt < NKT) {
                    int kg = ((kt < 4) ? kt * 16 : (kt - 4) * 16) + cc + hf * 8;
                    const float* src = (kt < 4)
                        ? whh  + ((size_t)li * GG + grow) * HH + kg
                        : wihR + ((size_t)(li - 1) * GG + grow) * HH + kg;
                    float2 wv = *reinterpret_cast<const float2*>(src);
                    bhi[gi][kt][hf] = packh(__float2half_rn(wv.x),
                                            __float2half_rn(wv.y));
                }
            }
    }
    float bs[4][2], ws[4][2];
    #pragma unroll
    for (int gi = 0; gi < 4; gi++)
        #pragma unroll
        for (int e = 0; e < 2; e++) {
            int gu = gi * 64 + u0 + e;
            bs[gi][e] = bih[li * GG + gu] + bhh[li * GG + gu];
            ws[gi][e] = L0 ? wih0[gu] : 0.f;
        }

    for (int i = tid; i < RPC * AST; i += 256) {
        (&Hh[0][0][0])[i] = __float2half(0.f);
        (&Hl[0][0][0])[i] = __float2half(0.f);
    }

    // stager: thread covers rows (srow, srow+8), unit pair su
    const int srow = tid >> 5;
    const int su   = 2 * ln;
    const size_t pb0 = ((size_t)(r0 + srow) * TT) * 64 + su;
    const size_t pb1 = ((size_t)(r0 + srow + 8) * TT) * 64 + su;
    const int* pf = li ? &g_flags[li - 1][ch] : nullptr;
    int* myf = &g_flags[li][ch];
    const float* hp = li ? g_h[li - 1] : nullptr;
    float* ho = g_h[li];
    float2 q0 = make_float2(0.f, 0.f), q1 = make_float2(0.f, 0.f);
    float qx = 0.f;

    // prologue: stage ring slots 0..1, prefetch slot 2 into regs (skew 3)
    if (!L0) {
        while (ld_acquire(pf) < 2) __nanosleep(64);
        #pragma unroll
        for (int s = 0; s < 2; s++) {
            sts_pair(&Xh[s][srow][su],     &Xl[s][srow][su],
                     *(const float2*)(hp + pb0 + (size_t)s * 64));
            sts_pair(&Xh[s][srow + 8][su], &Xl[s][srow + 8][su],
                     *(const float2*)(hp + pb1 + (size_t)s * 64));
        }
        while (ld_acquire(pf) < 3) __nanosleep(64);
        q0 = *(const float2*)(hp + pb0 + 2 * 64);
        q1 = *(const float2*)(hp + pb1 + 2 * 64);
    } else if (tid < RPC) {
        const float* xp = x + (size_t)(r0 + tid) * TT;
        xs0[0][tid] = xp[0];
        xs0[1][tid] = xp[1];
        qx = xp[2];
    }
    float c0 = 0.f, c1 = 0.f, c2 = 0.f, c3 = 0.f;
    __syncthreads();

    // dX = bias + x-contribution for the UPCOMING step (slot t).
    float dX[4][4];
    {
        #pragma unroll
        for (int gi = 0; gi < 4; gi++) {
            dX[gi][0] = bs[gi][0]; dX[gi][1] = bs[gi][1];
            dX[gi][2] = bs[gi][0]; dX[gi][3] = bs[gi][1];
        }
        if (!L0) {
            const __half* XhN = &Xh[0][0][0];
            const __half* XlN = &Xl[0][0][0];
            #pragma unroll
            for (int kt = 0; kt < 4; kt++) {
                int k0 = kt * 16;
                unsigned a0 = *(const unsigned*)(XhN + rA * AST + k0 + cc);
                unsigned a1 = *(const unsigned*)(XhN + (rA + 8) * AST + k0 + cc);
                unsigned a2 = *(const unsigned*)(XhN + rA * AST + k0 + cc + 8);
                unsigned a3 = *(const unsigned*)(XhN + (rA + 8) * AST + k0 + cc + 8);
                unsigned e0 = *(const unsigned*)(XlN + rA * AST + k0 + cc);
                unsigned e1 = *(const unsigned*)(XlN + (rA + 8) * AST + k0 + cc);
                unsigned e2 = *(const unsigned*)(XlN + rA * AST + k0 + cc + 8);
                unsigned e3 = *(const unsigned*)(XlN + (rA + 8) * AST + k0 + cc + 8);
                #pragma unroll
                for (int gi = 0; gi < 4; gi++) {
                    MMA(dX[gi][0], dX[gi][1], dX[gi][2], dX[gi][3],
                        a0, a1, a2, a3, bhi[gi][kt + 4][0], bhi[gi][kt + 4][1]);
                    MMA(dX[gi][0], dX[gi][1], dX[gi][2], dX[gi][3],
                        e0, e1, e2, e3, bhi[gi][kt + 4][0], bhi[gi][kt + 4][1]);
                }
            }
        } else {
            float xA = xs0[0][rA], xB = xs0[0][rA + 8];
            #pragma unroll
            for (int gi = 0; gi < 4; gi++) {
                dX[gi][0] += ws[gi][0] * xA; dX[gi][1] += ws[gi][1] * xA;
                dX[gi][2] += ws[gi][0] * xB; dX[gi][3] += ws[gi][1] * xB;
            }
        }
    }

    for (int t = 0; t < TT; ++t) {
        // ---- post-barrier critical path: h-part (2 chains, depth 4) ----
        float dM[4][4], dS[4][4];
        #pragma unroll
        for (int gi = 0; gi < 4; gi++)
            #pragma unroll
            for (int e = 0; e < 4; e++) { dM[gi][e] = dX[gi][e]; dS[gi][e] = 0.f; }

        const __half* HhT = &Hh[t & 1][0][0];
        const __half* HlT = &Hl[t & 1][0][0];
        #pragma unroll
        for (int kt = 0; kt < 4; kt++) {
            int k0 = kt * 16;
            unsigned a0 = *(const unsigned*)(HhT + rA * AST + k0 + cc);
            unsigned a1 = *(const unsigned*)(HhT + (rA + 8) * AST + k0 + cc);
            unsigned a2 = *(const unsigned*)(HhT + rA * AST + k0 + cc + 8);
            unsigned a3 = *(const unsigned*)(HhT + (rA + 8) * AST + k0 + cc + 8);
            unsigned e0 = *(const unsigned*)(HlT + rA * AST + k0 + cc);
            unsigned e1 = *(const unsigned*)(HlT + (rA + 8) * AST + k0 + cc);
            unsigned e2 = *(const unsigned*)(HlT + rA * AST + k0 + cc + 8);
            unsigned e3 = *(const unsigned*)(HlT + (rA + 8) * AST + k0 + cc + 8);
            #pragma unroll
            for (int gi = 0; gi < 4; gi++) {
                MMA(dM[gi][0], dM[gi][1], dM[gi][2], dM[gi][3],
                    a0, a1, a2, a3, bhi[gi][kt][0], bhi[gi][kt][1]);
                MMA(dS[gi][0], dS[gi][1], dS[gi][2], dS[gi][3],
                    e0, e1, e2, e3, bhi[gi][kt][0], bhi[gi][kt][1]);
            }
        }

        // ---- in-register LSTM cell update (single-MUFU activations) ----
        float hv0, hv1, hv2, hv3;
        { float iv = sig_fast(dM[0][0] + dS[0][0]), fv = sig_fast(dM[1][0] + dS[1][0]),
                gv = tanh_fast(dM[2][0] + dS[2][0]), ov = sig_fast(dM[3][0] + dS[3][0]);
          c0 = fv * c0 + iv * gv; hv0 = ov * tanh_fast(c0); }
        { float iv = sig_fast(dM[0][1] + dS[0][1]), fv = sig_fast(dM[1][1] + dS[1][1]),
                gv = tanh_fast(dM[2][1] + dS[2][1]), ov = sig_fast(dM[3][1] + dS[3][1]);
          c1 = fv * c1 + iv * gv; hv1 = ov * tanh_fast(c1); }
        { float iv = sig_fast(dM[0][2] + dS[0][2]), fv = sig_fast(dM[1][2] + dS[1][2]),
                gv = tanh_fast(dM[2][2] + dS[2][2]), ov = sig_fast(dM[3][2] + dS[3][2]);
          c2 = fv * c2 + iv * gv; hv2 = ov * tanh_fast(c2); }
        { float iv = sig_fast(dM[0][3] + dS[0][3]), fv = sig_fast(dM[1][3] + dS[1][3]),
                gv = tanh_fast(dM[2][3] + dS[2][3]), ov = sig_fast(dM[3][3] + dS[3][3]);
          c3 = fv * c3 + iv * gv; hv3 = ov * tanh_fast(c3); }

        const int ns = (t + 1) & 1;
        sts_pair(&Hh[ns][rA][u0],     &Hl[ns][rA][u0],     make_float2(hv0, hv1));
        sts_pair(&Hh[ns][rA + 8][u0], &Hl[ns][rA + 8][u0], make_float2(hv2, hv3));
        *(float2*)(ho + ((size_t)(r0 + rA) * TT + t) * 64 + u0)     = make_float2(hv0, hv1);
        *(float2*)(ho + ((size_t)(r0 + rA + 8) * TT + t) * 64 + u0) = make_float2(hv2, hv3);

        // ---- pre-barrier: x-part for step t+1 (ring slot t+1) ----
        if (t + 1 < TT) {
            #pragma unroll
            for (int gi = 0; gi < 4; gi++) {
                dX[gi][0] = bs[gi][0]; dX[gi][1] = bs[gi][1];
                dX[gi][2] = bs[gi][0]; dX[gi][3] = bs[gi][1];
            }
            if (!L0) {
                const __half* XhN = &Xh[(t + 1) & (NRING - 1)][0][0];
                const __half* XlN = &Xl[(t + 1) & (NRING - 1)][0][0];
                #pragma unroll
                for (int kt = 0; kt < 4; kt++) {
                    int k0 = kt * 16;
                    unsigned a0 = *(const unsigned*)(XhN + rA * AST + k0 + cc);
                    unsigned a1 = *(const unsigned*)(XhN + (rA + 8) * AST + k0 + cc);
                    unsigned a2 = *(const unsigned*)(XhN + rA * AST + k0 + cc + 8);
                    unsigned a3 = *(const unsigned*)(XhN + (rA + 8) * AST + k0 + cc + 8);
                    unsigned e0 = *(const unsigned*)(XlN + rA * AST + k0 + cc);
                    unsigned e1 = *(const unsigned*)(XlN + (rA + 8) * AST + k0 + cc);
                    unsigned e2 = *(const unsigned*)(XlN + rA * AST + k0 + cc + 8);
                    unsigned e3 = *(const unsigned*)(XlN + (rA + 8) * AST + k0 + cc + 8);
                    #pragma unroll
                    for (int gi = 0; gi < 4; gi++) {
                        MMA(dX[gi][0], dX[gi][1], dX[gi][2], dX[gi][3],
                            a0, a1, a2, a3, bhi[gi][kt + 4][0], bhi[gi][kt + 4][1]);
                        MMA(dX[gi][0], dX[gi][1], dX[gi][2], dX[gi][3],
                            e0, e1, e2, e3, bhi[gi][kt + 4][0], bhi[gi][kt + 4][1]);
                    }
                }
            } else {
                float xA = xs0[(t + 1) & (NRING - 1)][rA];
                float xB = xs0[(t + 1) & (NRING - 1)][rA + 8];
                #pragma unroll
                for (int gi = 0; gi < 4; gi++) {
                    dX[gi][0] += ws[gi][0] * xA; dX[gi][1] += ws[gi][1] * xA;
                    dX[gi][2] += ws[gi][0] * xB; dX[gi][3] += ws[gi][1] * xB;
                }
            }
        }

        // ---- staging: STS slot t+2 (prefetched), LDG slot t+3 ----
        if (!L0) {
            if (t + 2 < TT) {
                int sl = (t + 2) & (NRING - 1);
                sts_pair(&Xh[sl][srow][su],     &Xl[sl][srow][su],     q0);
                sts_pair(&Xh[sl][srow + 8][su], &Xl[sl][srow + 8][su], q1);
            }
            if (t + 3 < TT) {
                int fl = ld_acquire(pf);
                while (fl < t + 4) { __nanosleep(64); fl = ld_acquire(pf); }
                q0 = *(const float2*)(hp + pb0 + (size_t)(t + 3) * 64);
                q1 = *(const float2*)(hp + pb1 + (size_t)(t + 3) * 64);
            }
        } else if (tid < RPC) {
            if (t + 2 < TT) xs0[(t + 2) & (NRING - 1)][tid] = qx;
            if (t + 3 < TT) qx = x[(size_t)(r0 + tid) * TT + t + 3];
        }
        bool pub = (li < 4) && ((t & 1) == 1);
        __syncthreads();
        if (pub && tid == 0) st_release(myf, t + 1);  // release orders all CTA writes
    }
}

// ---------------------------------------------------------------------------
// Head: out = relu(relu(h) @ W1^T + b1) @ W2^T + b2.
// ---------------------------------------------------------------------------
__global__ void __launch_bounds__(256)
fc_kernel(const float* __restrict__ hin, const float* __restrict__ W1,
          const float* __restrict__ b1, const float* __restrict__ W2,
          const float* __restrict__ b2, float* __restrict__ out)
{
    __shared__ float W1T[64 * 64];
    __shared__ float b1s[64], w2s[64];
    __shared__ float hsm[8][64];
    for (int i = threadIdx.x; i < 4096; i += 256) {
        int j = i >> 6, k = i & 63;
        W1T[k * 64 + j] = W1[j * 64 + k];
    }
    if (threadIdx.x < 64) {
        b1s[threadIdx.x] = b1[threadIdx.x];
        w2s[threadIdx.x] = W2[threadIdx.x];
    }
    __syncthreads();
    const float b2v = b2[0];
    const int warp = threadIdx.x >> 5, lane = threadIdx.x & 31;
    for (int p = blockIdx.x * 8 + warp; p < BB * TT; p += gridDim.x * 8) {
        float h0 = fmaxf(hin[(size_t)p * 64 + lane], 0.f);
        float h1 = fmaxf(hin[(size_t)p * 64 + 32 + lane], 0.f);
        hsm[warp][lane] = h0; hsm[warp][lane + 32] = h1;
        __syncwarp();
        float y0 = b1s[lane], y1 = b1s[lane + 32];
        #pragma unroll
        for (int k = 0; k < 64; k++) {
            float hv = hsm[warp][k];
            y0 = fmaf(W1T[k * 64 + lane], hv, y0);
            y1 = fmaf(W1T[k * 64 + lane + 32], hv, y1);
        }
        float part = fmaxf(y0, 0.f) * w2s[lane] + fmaxf(y1, 0.f) * w2s[lane + 32];
        #pragma unroll
        for (int o = 16; o; o >>= 1) part += __shfl_down_sync(~0u, part, o);
        if (!lane) out[p] = part + b2v;
        __syncwarp();
    }
}

extern "C" void kernel_launch(void* const* d_in, const int* in_sizes, int n_in,
                              void* d_out, int out_size)
{
    const float* x    = (const float*)d_in[0];
    const float* wih0 = (const float*)d_in[1];
    const float* wihR = (const float*)d_in[2];
    const float* whh  = (const float*)d_in[3];
    const float* bih  = (const float*)d_in[4];
    const float* bhh  = (const float*)d_in[5];
    const float* W1   = (const float*)d_in[6];
    const float* b1   = (const float*)d_in[7];
    const float* W2   = (const float*)d_in[8];
    const float* b2   = (const float*)d_in[9];
    float* out = (float*)d_out;
    (void)in_sizes; (void)n_in; (void)out_size;

    void* pH = nullptr;
    cudaGetSymbolAddress(&pH, g_h);
    float* h4 = (float*)pH + 4 * (size_t)BB * TT * HH;

    reset_flags<<<1, 128>>>();
    wavefront<<<NL * CPL, 256>>>(x, wih0, wihR, whh, bih, bhh);
    fc_kernel<<<2048, 256>>>(h4, W1, b1, W2, b2, out);
}